// round 6
// baseline (speedup 1.0000x reference)
#include <cuda_runtime.h>
#include <cstdint>
#include <cstddef>

#define NTOK 8192
#define CDIM 512

// ---------------- scratch (device globals; no allocations allowed) ----------
__device__ __align__(16) float g_S1[(size_t)NTOK * NTOK];
__device__ __align__(16) float g_S2[(size_t)NTOK * NTOK];
__device__ __align__(16) float g_QK1[(size_t)NTOK * 128];
__device__ __align__(16) float g_QK2[(size_t)NTOK * 128];
__device__ __align__(16) float g_V1[(size_t)NTOK * CDIM];
__device__ __align__(16) float g_V2[(size_t)NTOK * CDIM];
__device__ __align__(16) float g_Wqk[(size_t)CDIM * 128];
__device__ __align__(16) float g_part[(size_t)2 * 64 * NTOK];
__device__ __align__(16) float g_rinv[2 * NTOK];

// ---------------- helpers ----------------------------------------------------
__device__ __forceinline__ uint32_t f2tf32(float x) {
    uint32_t r;
    asm("cvt.rna.tf32.f32 %0, %1;" : "=r"(r) : "f"(x));
    return r;
}
__device__ __forceinline__ float tf32_round(float x) { return __uint_as_float(f2tf32(x)); }

__device__ __forceinline__ void mma8(float* c, const uint32_t* a, const uint32_t* b) {
    asm volatile(
        "mma.sync.aligned.m16n8k8.row.col.f32.tf32.tf32.f32 "
        "{%0,%1,%2,%3}, {%4,%5,%6,%7}, {%8,%9}, {%0,%1,%2,%3};"
        : "+f"(c[0]), "+f"(c[1]), "+f"(c[2]), "+f"(c[3])
        : "r"(a[0]), "r"(a[1]), "r"(a[2]), "r"(a[3]), "r"(b[0]), "r"(b[1]));
}

__global__ void pack_wqk(const float* __restrict__ Wq, const float* __restrict__ Wk,
                         float* __restrict__ Wqk) {
    const int i = blockIdx.x * 256 + threadIdx.x;   // 512*128
    const int r = i >> 7, c = i & 127;
    Wqk[i] = (c < 64) ? Wq[r * 64 + c] : Wk[r * 64 + (c - 64)];
}

// ================= 3xTF32 error-compensated GEMM (Q/K projections) ===========
// 256 threads, block 128x128, warp tile 64x32. B row-major [K x N], transposed.
__global__ __launch_bounds__(256, 2)
void gemm3x(const float* __restrict__ A0, const float* __restrict__ A1, int lda,
            const float* __restrict__ B0, const float* __restrict__ B1, int ldb,
            float* __restrict__ C0, float* __restrict__ C1, int ldc, int K)
{
    constexpr int BK = 16, STR = BK + 8;
    __shared__ float As[2][128][STR];
    __shared__ float Bs[2][128][STR];

    const float* A = blockIdx.z ? A1 : A0;
    const float* B = blockIdx.z ? B1 : B0;
    float*       C = blockIdx.z ? C1 : C0;

    const int tid  = threadIdx.x;
    const int lane = tid & 31;
    const int wid  = tid >> 5;
    const int wm0  = (wid & 1) << 6;
    const int wn0  = (wid >> 1) << 5;
    const int lr   = lane >> 2;
    const int lc2  = (lane & 3) << 1;

    const size_t row0 = (size_t)blockIdx.y * 128;
    const size_t col0 = (size_t)blockIdx.x * 128;

    const int ar = tid >> 2;
    const int ac = (tid & 3) << 2;
    const float* Ap0 = A + (row0 + ar) * (size_t)lda + ac;
    const float* Ap1 = Ap0 + (size_t)64 * lda;

    const int bk_ = tid & 15;
    const int bg4 = (tid >> 4) << 2;
    const float* Bp0 = B + (size_t)bk_ * ldb + col0 + bg4;
    const float* Bp1 = Bp0 + 64;

    float4 a0 = *(const float4*)Ap0;
    float4 a1 = *(const float4*)Ap1;
    float4 b0 = *(const float4*)Bp0;
    float4 b1 = *(const float4*)Bp1;

    float acc[4][4][4];
#pragma unroll
    for (int i = 0; i < 4; i++)
#pragma unroll
        for (int j = 0; j < 4; j++)
#pragma unroll
            for (int k = 0; k < 4; k++) acc[i][j][k] = 0.f;

    auto store_tiles = [&](int bf, float4 sa0, float4 sa1, float4 sb0, float4 sb1) {
        *(float4*)&As[bf][ar][ac]      = sa0;
        *(float4*)&As[bf][ar + 64][ac] = sa1;
        Bs[bf][bg4 + 0][bk_] = sb0.x;
        Bs[bf][bg4 + 1][bk_] = sb0.y;
        Bs[bf][bg4 + 2][bk_] = sb0.z;
        Bs[bf][bg4 + 3][bk_] = sb0.w;
        Bs[bf][bg4 + 64][bk_] = sb1.x;
        Bs[bf][bg4 + 65][bk_] = sb1.y;
        Bs[bf][bg4 + 66][bk_] = sb1.z;
        Bs[bf][bg4 + 67][bk_] = sb1.w;
    };

    auto compute = [&](int bf) {
#pragma unroll
        for (int kk = 0; kk < BK; kk += 8) {
            uint32_t ah[4][4], al[4][4], bh[4][2], bl[4][2];
#pragma unroll
            for (int mt = 0; mt < 4; mt++) {
                const float2 t0 = *(const float2*)&As[bf][wm0 + mt * 16 + lr][kk + lc2];
                const float2 t1 = *(const float2*)&As[bf][wm0 + mt * 16 + lr + 8][kk + lc2];
                ah[mt][0] = f2tf32(t0.x); al[mt][0] = __float_as_uint(t0.x - __uint_as_float(ah[mt][0]));
                ah[mt][2] = f2tf32(t0.y); al[mt][2] = __float_as_uint(t0.y - __uint_as_float(ah[mt][2]));
                ah[mt][1] = f2tf32(t1.x); al[mt][1] = __float_as_uint(t1.x - __uint_as_float(ah[mt][1]));
                ah[mt][3] = f2tf32(t1.y); al[mt][3] = __float_as_uint(t1.y - __uint_as_float(ah[mt][3]));
            }
#pragma unroll
            for (int nt = 0; nt < 4; nt++) {
                const float2 t = *(const float2*)&Bs[bf][wn0 + nt * 8 + lr][kk + lc2];
                bh[nt][0] = f2tf32(t.x); bl[nt][0] = __float_as_uint(t.x - __uint_as_float(bh[nt][0]));
                bh[nt][1] = f2tf32(t.y); bl[nt][1] = __float_as_uint(t.y - __uint_as_float(bh[nt][1]));
            }
#pragma unroll
            for (int mt = 0; mt < 4; mt++)
#pragma unroll
                for (int nt = 0; nt < 4; nt++) {
                    mma8(acc[mt][nt], ah[mt], bh[nt]);
                    mma8(acc[mt][nt], al[mt], bh[nt]);
                    mma8(acc[mt][nt], ah[mt], bl[nt]);
                }
        }
    };

    store_tiles(0, a0, a1, b0, b1);
    __syncthreads();

    const int KT = K / BK;
    int buf = 0;
    for (int t = 1; t <= KT; t++) {
        if (t < KT) {
            const int ko = t * BK;
            a0 = *(const float4*)(Ap0 + ko);
            a1 = *(const float4*)(Ap1 + ko);
            b0 = *(const float4*)(Bp0 + (size_t)ko * ldb);
            b1 = *(const float4*)(Bp1 + (size_t)ko * ldb);
        }
        compute(buf);
        if (t < KT) {
            buf ^= 1;
            store_tiles(buf, a0, a1, b0, b1);
            __syncthreads();
        }
    }

#pragma unroll
    for (int mt = 0; mt < 4; mt++) {
#pragma unroll
        for (int h = 0; h < 2; h++) {
            const size_t r = row0 + wm0 + mt * 16 + lr + h * 8;
            float* Crow = C + r * (size_t)ldc + col0;
#pragma unroll
            for (int nt = 0; nt < 4; nt++) {
                const int cc = wn0 + nt * 8 + lc2;
                float2 v;
                v.x = acc[mt][nt][h * 2 + 0];
                v.y = acc[mt][nt][h * 2 + 1];
                *(float2*)(Crow + cc) = v;
            }
        }
    }
}

// ================= logits kernel: S = tf32(exp(Q @ K^T)), partial row sums ===
// 3xTF32 with hi/lo split done ONCE at staging. K=64. No max subtraction
// (|logit| <~ 60 << 88 so exp cannot overflow). Deterministic partial row sums.
__global__ __launch_bounds__(256, 2)
void logits_kernel(const float* __restrict__ QA0, const float* __restrict__ QA1,
                   const float* __restrict__ KB0, const float* __restrict__ KB1,
                   float* __restrict__ S0, float* __restrict__ S1p,
                   float* __restrict__ part)
{
    constexpr int STR = 24;
    __shared__ float Ah[128][STR], Al[128][STR], Bh[128][STR], Bl[128][STR];

    const int z = blockIdx.z;
    const float* A = z ? QA1 : QA0;
    const float* B = z ? KB1 : KB0;
    float* S = z ? S1p : S0;

    const int tid  = threadIdx.x;
    const int lane = tid & 31;
    const int wid  = tid >> 5;
    const int wm0  = (wid & 1) << 6;
    const int wn0  = (wid >> 1) << 5;
    const int lr   = lane >> 2;
    const int lc2  = (lane & 3) << 1;

    const size_t row0 = (size_t)blockIdx.y * 128;
    const size_t col0 = (size_t)blockIdx.x * 128;

    const int sr = tid >> 1;
    const int sc = (tid & 1) << 3;
    const float* Apt = A + (row0 + sr) * 128 + sc;
    const float* Bpt = B + (col0 + sr) * 128 + sc;

    float acc[4][4][4];
#pragma unroll
    for (int i = 0; i < 4; i++)
#pragma unroll
        for (int j = 0; j < 4; j++)
#pragma unroll
            for (int k = 0; k < 4; k++) acc[i][j][k] = 0.f;

    float4 ra0 = *(const float4*)Apt;
    float4 ra1 = *(const float4*)(Apt + 4);
    float4 rb0 = *(const float4*)Bpt;
    float4 rb1 = *(const float4*)(Bpt + 4);

    auto put = [&](float (*H)[STR], float (*L)[STR], int c, float v) {
        const float h = tf32_round(v);
        H[sr][c] = h;
        L[sr][c] = v - h;
    };

    for (int t = 0; t < 4; t++) {
        put(Ah, Al, sc + 0, ra0.x); put(Ah, Al, sc + 1, ra0.y);
        put(Ah, Al, sc + 2, ra0.z); put(Ah, Al, sc + 3, ra0.w);
        put(Ah, Al, sc + 4, ra1.x); put(Ah, Al, sc + 5, ra1.y);
        put(Ah, Al, sc + 6, ra1.z); put(Ah, Al, sc + 7, ra1.w);
        put(Bh, Bl, sc + 0, rb0.x); put(Bh, Bl, sc + 1, rb0.y);
        put(Bh, Bl, sc + 2, rb0.z); put(Bh, Bl, sc + 3, rb0.w);
        put(Bh, Bl, sc + 4, rb1.x); put(Bh, Bl, sc + 5, rb1.y);
        put(Bh, Bl, sc + 6, rb1.z); put(Bh, Bl, sc + 7, rb1.w);
        __syncthreads();
        if (t < 3) {
            const int ko = (t + 1) * 16;
            ra0 = *(const float4*)(Apt + ko);
            ra1 = *(const float4*)(Apt + ko + 4);
            rb0 = *(const float4*)(Bpt + ko);
            rb1 = *(const float4*)(Bpt + ko + 4);
        }
#pragma unroll
        for (int kk = 0; kk < 16; kk += 8) {
            uint32_t ah[4][4], al[4][4], bh[4][2], bl[4][2];
#pragma unroll
            for (int mt = 0; mt < 4; mt++) {
                const int r0i = wm0 + mt * 16 + lr;
                const float2 h0 = *(const float2*)&Ah[r0i][kk + lc2];
                const float2 h1 = *(const float2*)&Ah[r0i + 8][kk + lc2];
                const float2 l0 = *(const float2*)&Al[r0i][kk + lc2];
                const float2 l1 = *(const float2*)&Al[r0i + 8][kk + lc2];
                ah[mt][0] = __float_as_uint(h0.x); ah[mt][1] = __float_as_uint(h1.x);
                ah[mt][2] = __float_as_uint(h0.y); ah[mt][3] = __float_as_uint(h1.y);
                al[mt][0] = __float_as_uint(l0.x); al[mt][1] = __float_as_uint(l1.x);
                al[mt][2] = __float_as_uint(l0.y); al[mt][3] = __float_as_uint(l1.y);
            }
#pragma unroll
            for (int nt = 0; nt < 4; nt++) {
                const int nn = wn0 + nt * 8 + lr;
                const float2 h = *(const float2*)&Bh[nn][kk + lc2];
                const float2 l = *(const float2*)&Bl[nn][kk + lc2];
                bh[nt][0] = __float_as_uint(h.x); bh[nt][1] = __float_as_uint(h.y);
                bl[nt][0] = __float_as_uint(l.x); bl[nt][1] = __float_as_uint(l.y);
            }
#pragma unroll
            for (int mt = 0; mt < 4; mt++)
#pragma unroll
                for (int nt = 0; nt < 4; nt++) {
                    mma8(acc[mt][nt], ah[mt], bh[nt]);
                    mma8(acc[mt][nt], al[mt], bh[nt]);
                    mma8(acc[mt][nt], ah[mt], bl[nt]);
                }
        }
        __syncthreads();
    }

    // epilogue: exp, tf32-round, store, deterministic per-row partial sums
    float* red = &Ah[0][0];
#pragma unroll
    for (int mt = 0; mt < 4; mt++) {
#pragma unroll
        for (int h = 0; h < 2; h++) {
            const int rl = wm0 + mt * 16 + lr + 8 * h;
            float* Crow = S + (row0 + rl) * (size_t)NTOK + col0;
            float es = 0.f;
#pragma unroll
            for (int nt = 0; nt < 4; nt++) {
                const int cc = wn0 + nt * 8 + lc2;
                float2 v;
                v.x = tf32_round(__expf(acc[mt][nt][h * 2 + 0]));
                v.y = tf32_round(__expf(acc[mt][nt][h * 2 + 1]));
                es += v.x + v.y;
                *(float2*)(Crow + cc) = v;
            }
            es += __shfl_xor_sync(0xffffffffu, es, 1);
            es += __shfl_xor_sync(0xffffffffu, es, 2);
            if ((lane & 3) == 0) red[(wid >> 1) * 128 + rl] = es;
        }
    }
    __syncthreads();
    if (tid < 128) {
        const float s = red[tid] + red[128 + tid] + red[256 + tid] + red[384 + tid];
        part[((size_t)z * 64 + blockIdx.x) * NTOK + row0 + tid] = s;
    }
}

__global__ void reduce_rinv(const float* __restrict__ part, float* __restrict__ rinv) {
    const int i = blockIdx.x * 256 + threadIdx.x;   // 0..16383
    const int z = i >> 13, r = i & (NTOK - 1);
    const float* p = part + (size_t)z * 64 * NTOK + r;
    float s = 0.f;
#pragma unroll
    for (int b = 0; b < 64; b++) s += p[(size_t)b * NTOK];
    rinv[i] = 1.f / s;
}

// ================= fast single-pass TF32 GEMM (R4-proven layout) =============
// 128 threads, block 128x128, warp tile 64x64. B row-major [K x N], transposed
// into smem (float2 fragment loads). z batches two problems.
// MODE 0 (V-proj): stage with tf32-rna rounding, output rounded to tf32.
// MODE 1 (PV):     stage pure copy (operands already tf32-exact),
//                  epilogue: C = acc * rinv[row] + Res.
template<int MODE>
__global__ __launch_bounds__(128, 2)
void gemm_fast(const float* __restrict__ A0, const float* __restrict__ A1, int lda,
               const float* __restrict__ B0, const float* __restrict__ B1, int ldb,
               const float* __restrict__ R0, const float* __restrict__ R1,
               float* __restrict__ C0, float* __restrict__ C1, int ldc, int K,
               const float* __restrict__ RI)
{
    constexpr int STR = 24;
    __shared__ float As[2][128][STR];
    __shared__ float Bs[2][128][STR];

    const int z = blockIdx.z;
    const float* A   = z ? A1 : A0;
    const float* B   = z ? B1 : B0;
    const float* Res = z ? R1 : R0;
    float*       C   = z ? C1 : C0;

    const int tid  = threadIdx.x;
    const int lane = tid & 31;
    const int wid  = tid >> 5;
    const int wm0  = (wid & 1) << 6;
    const int wn0  = (wid >> 1) << 6;
    const int lr   = lane >> 2;
    const int lc2  = (lane & 3) << 1;

    const size_t row0 = (size_t)blockIdx.y * 128;
    const size_t col0 = (size_t)blockIdx.x * 128;

    const int arr = tid >> 2;
    const int ac4 = (tid & 3) << 2;
    const float* Apb = A + (row0 + arr) * (size_t)lda + ac4;
    const size_t astr = (size_t)32 * lda;

    const int bk  = tid & 15;
    const int bn0 = (tid >> 4) << 4;
    const float* Bpb = B + (size_t)bk * ldb + col0 + bn0;

    float acc[4][8][4];
#pragma unroll
    for (int i = 0; i < 4; i++)
#pragma unroll
        for (int j = 0; j < 8; j++)
#pragma unroll
            for (int k = 0; k < 4; k++) acc[i][j][k] = 0.f;

    auto stage = [&](int bf, const float4* av, const float4* bv) {
#pragma unroll
        for (int j = 0; j < 4; j++) {
            float4 v = av[j];
            if (MODE == 0) {
                v.x = tf32_round(v.x); v.y = tf32_round(v.y);
                v.z = tf32_round(v.z); v.w = tf32_round(v.w);
            }
            *(float4*)&As[bf][arr + 32 * j][ac4] = v;
        }
#pragma unroll
        for (int i = 0; i < 4; i++) {
            float4 v = bv[i];
            if (MODE == 0) {
                v.x = tf32_round(v.x); v.y = tf32_round(v.y);
                v.z = tf32_round(v.z); v.w = tf32_round(v.w);
            }
            const int nb = bn0 + 4 * i;
            Bs[bf][nb + 0][bk] = v.x;
            Bs[bf][nb + 1][bk] = v.y;
            Bs[bf][nb + 2][bk] = v.z;
            Bs[bf][nb + 3][bk] = v.w;
        }
    };

    float4 av[4], bv[4];
#pragma unroll
    for (int j = 0; j < 4; j++) av[j] = *(const float4*)(Apb + j * astr);
#pragma unroll
    for (int i = 0; i < 4; i++) bv[i] = *(const float4*)(Bpb + 4 * i);
    stage(0, av, bv);
    __syncthreads();

    const int KT = K / 16;
    int buf = 0;
    for (int t = 1; t <= KT; t++) {
        if (t < KT) {
            const size_t ko = (size_t)t * 16;
#pragma unroll
            for (int j = 0; j < 4; j++) av[j] = *(const float4*)(Apb + j * astr + ko);
#pragma unroll
            for (int i = 0; i < 4; i++) bv[i] = *(const float4*)(Bpb + ko * ldb + 4 * i);
        }
#pragma unroll
        for (int kk = 0; kk < 16; kk += 8) {
            uint32_t ah[4][4], bh[8][2];
#pragma unroll
            for (int mt = 0; mt < 4; mt++) {
                const float2 t0 = *(const float2*)&As[buf][wm0 + mt * 16 + lr][kk + lc2];
                const float2 t1 = *(const float2*)&As[buf][wm0 + mt * 16 + lr + 8][kk + lc2];
                ah[mt][0] = __float_as_uint(t0.x);
                ah[mt][1] = __float_as_uint(t1.x);
                ah[mt][2] = __float_as_uint(t0.y);
                ah[mt][3] = __float_as_uint(t1.y);
            }
#pragma unroll
            for (int nt = 0; nt < 8; nt++) {
                const float2 t = *(const float2*)&Bs[buf][wn0 + nt * 8 + lr][kk + lc2];
                bh[nt][0] = __float_as_uint(t.x);
                bh[nt][1] = __float_as_uint(t.y);
            }
#pragma unroll
            for (int mt = 0; mt < 4; mt++)
#pragma unroll
                for (int nt = 0; nt < 8; nt++)
                    mma8(acc[mt][nt], ah[mt], bh[nt]);
        }
        if (t < KT) {
            buf ^= 1;
            stage(buf, av, bv);
            __syncthreads();
        }
    }

    // epilogue
#pragma unroll
    for (int mt = 0; mt < 4; mt++) {
#pragma unroll
        for (int h = 0; h < 2; h++) {
            const size_t r = row0 + wm0 + mt * 16 + lr + h * 8;
            const float scale = (MODE == 1) ? RI[(size_t)z * NTOK + r] : 1.f;
            float* Crow = C + r * (size_t)ldc + col0;
            const float* Rrow = (MODE == 1) ? (Res + r * (size_t)ldc + col0) : nullptr;
#pragma unroll
            for (int nt = 0; nt < 8; nt++) {
                const int cc = wn0 + nt * 8 + lc2;
                float2 v;
                v.x = acc[mt][nt][h * 2 + 0];
                v.y = acc[mt][nt][h * 2 + 1];
                if (MODE == 1) {
                    const float2 rv = *(const float2*)(Rrow + cc);
                    v.x = v.x * scale + rv.x;
                    v.y = v.y * scale + rv.y;
                } else {
                    v.x = tf32_round(v.x);
                    v.y = tf32_round(v.y);
                }
                *(float2*)(Crow + cc) = v;
            }
        }
    }
}

// ---------------- launch -----------------------------------------------------
extern "C" void kernel_launch(void* const* d_in, const int* in_sizes, int n_in,
                              void* d_out, int out_size)
{
    const float* im1 = (const float*)d_in[0];
    const float* im2 = (const float*)d_in[1];
    const float* Wq  = (const float*)d_in[2];
    const float* Wk  = (const float*)d_in[3];
    const float* Wv  = (const float*)d_in[4];

    float* out1 = (float*)d_out;
    float* out2 = out1 + (size_t)NTOK * CDIM;

    float *pS1, *pS2, *pQK1, *pQK2, *pV1, *pV2, *pWqk, *pPart, *pRinv;
    cudaGetSymbolAddress((void**)&pS1,   g_S1);
    cudaGetSymbolAddress((void**)&pS2,   g_S2);
    cudaGetSymbolAddress((void**)&pQK1,  g_QK1);
    cudaGetSymbolAddress((void**)&pQK2,  g_QK2);
    cudaGetSymbolAddress((void**)&pV1,   g_V1);
    cudaGetSymbolAddress((void**)&pV2,   g_V2);
    cudaGetSymbolAddress((void**)&pWqk,  g_Wqk);
    cudaGetSymbolAddress((void**)&pPart, g_part);
    cudaGetSymbolAddress((void**)&pRinv, g_rinv);

    pack_wqk<<<256, 256>>>(Wq, Wk, pWqk);

    // Q/K projections (3xTF32, near-fp32): [Q|K]z = imz @ [Wq|Wk]
    gemm3x<<<dim3(1, 64, 2), 256>>>(im1, im2, CDIM, pWqk, pWqk, 128,
                                    pQK1, pQK2, 128, CDIM);
    // V projections (single-pass tf32, staged rna rounding, rounded outputs)
    gemm_fast<0><<<dim3(4, 64, 2), 128>>>(im1, im2, CDIM, Wv, Wv, CDIM,
                                          nullptr, nullptr, pV1, pV2, CDIM,
                                          CDIM, nullptr);
    // logits + exp + partial row sums:  S1 = exp(Q2 K1^T),  S2 = exp(Q1 K2^T)
    logits_kernel<<<dim3(64, 64, 2), 256>>>(pQK2, pQK1, pQK1 + 64, pQK2 + 64,
                                            pS1, pS2, pPart);
    reduce_rinv<<<64, 256>>>(pPart, pRinv);
    // PV: out = (S @ V) * rinv + im   (pure-copy staging, exact tf32 operands)
    gemm_fast<1><<<dim3(4, 64, 2), 128>>>(pS1, pS2, NTOK, pV1, pV2, CDIM,
                                          im1, im2, out1, out2, CDIM,
                                          NTOK, pRinv);
}

// round 7
// speedup vs baseline: 1.2596x; 1.2596x over previous
#include <cuda_runtime.h>
#include <cstdint>
#include <cstddef>

#define NTOK 8192
#define CDIM 512

// ---------------- scratch (device globals; no allocations allowed) ----------
__device__ __align__(16) float g_S1[(size_t)NTOK * NTOK];
__device__ __align__(16) float g_S2[(size_t)NTOK * NTOK];
__device__ __align__(16) float g_QK1[(size_t)NTOK * 128];
__device__ __align__(16) float g_QK2[(size_t)NTOK * 128];
__device__ __align__(16) float g_V1[(size_t)NTOK * CDIM];
__device__ __align__(16) float g_V2[(size_t)NTOK * CDIM];
__device__ __align__(16) float g_Wqk[(size_t)CDIM * 128];
__device__ __align__(16) float g_part[(size_t)2 * 64 * NTOK];
__device__ __align__(16) float g_rinv[2 * NTOK];

// ---------------- helpers ----------------------------------------------------
__device__ __forceinline__ uint32_t f2tf32(float x) {
    uint32_t r;
    asm("cvt.rna.tf32.f32 %0, %1;" : "=r"(r) : "f"(x));
    return r;
}
__device__ __forceinline__ float tf32_round(float x) { return __uint_as_float(f2tf32(x)); }

__device__ __forceinline__ void mma8(float* c, const uint32_t* a, const uint32_t* b) {
    asm volatile(
        "mma.sync.aligned.m16n8k8.row.col.f32.tf32.tf32.f32 "
        "{%0,%1,%2,%3}, {%4,%5,%6,%7}, {%8,%9}, {%0,%1,%2,%3};"
        : "+f"(c[0]), "+f"(c[1]), "+f"(c[2]), "+f"(c[3])
        : "r"(a[0]), "r"(a[1]), "r"(a[2]), "r"(a[3]), "r"(b[0]), "r"(b[1]));
}

__global__ void pack_wqk(const float* __restrict__ Wq, const float* __restrict__ Wk,
                         float* __restrict__ Wqk) {
    const int i = blockIdx.x * 256 + threadIdx.x;   // 512*128
    const int r = i >> 7, c = i & 127;
    Wqk[i] = (c < 64) ? Wq[r * 64 + c] : Wk[r * 64 + (c - 64)];
}

// ================= 3xTF32 error-compensated GEMM (R4-proven body) ============
// 256 threads, block 128x128, warp tile 64x32. z batches two problems.
// TRB=true : B row-major [K x N] (transposed into smem)  -- projections
// TRB=false: B row-major [N x K]                          -- logits (Q @ K^T)
// EXPSUM   : epilogue writes tf32(exp(acc)) and per-row partial sums to part.
template<bool TRB, bool EXPSUM>
__global__ __launch_bounds__(256, 2)
void gemm3x(const float* __restrict__ A0, const float* __restrict__ A1, int lda,
            const float* __restrict__ B0, const float* __restrict__ B1, int ldb,
            float* __restrict__ C0, float* __restrict__ C1, int ldc, int K,
            float* __restrict__ part)
{
    constexpr int BK = 16, STR = BK + 8;
    __shared__ float As[2][128][STR];
    __shared__ float Bs[2][128][STR];

    const int z = blockIdx.z;
    const float* A = z ? A1 : A0;
    const float* B = z ? B1 : B0;
    float*       C = z ? C1 : C0;

    const int tid  = threadIdx.x;
    const int lane = tid & 31;
    const int wid  = tid >> 5;
    const int wm0  = (wid & 1) << 6;
    const int wn0  = (wid >> 1) << 5;
    const int lr   = lane >> 2;
    const int lc2  = (lane & 3) << 1;

    const size_t row0 = (size_t)blockIdx.y * 128;
    const size_t col0 = (size_t)blockIdx.x * 128;

    const int ar = tid >> 2;
    const int ac = (tid & 3) << 2;
    const float* Ap0 = A + (row0 + ar) * (size_t)lda + ac;
    const float* Ap1 = Ap0 + (size_t)64 * lda;

    const float *Bp0, *Bp1;
    int bk_ = 0, bg4 = 0;
    if (TRB) {
        bk_ = tid & 15;
        bg4 = (tid >> 4) << 2;
        Bp0 = B + (size_t)bk_ * ldb + col0 + bg4;
        Bp1 = Bp0 + 64;
    } else {
        Bp0 = B + (col0 + ar) * (size_t)ldb + ac;
        Bp1 = Bp0 + (size_t)64 * ldb;
    }

    float4 a0 = *(const float4*)Ap0;
    float4 a1 = *(const float4*)Ap1;
    float4 b0 = *(const float4*)Bp0;
    float4 b1 = *(const float4*)Bp1;

    float acc[4][4][4];
#pragma unroll
    for (int i = 0; i < 4; i++)
#pragma unroll
        for (int j = 0; j < 4; j++)
#pragma unroll
            for (int k = 0; k < 4; k++) acc[i][j][k] = 0.f;

    auto store_tiles = [&](int bf, float4 sa0, float4 sa1, float4 sb0, float4 sb1) {
        *(float4*)&As[bf][ar][ac]      = sa0;
        *(float4*)&As[bf][ar + 64][ac] = sa1;
        if (TRB) {
            Bs[bf][bg4 + 0][bk_] = sb0.x;
            Bs[bf][bg4 + 1][bk_] = sb0.y;
            Bs[bf][bg4 + 2][bk_] = sb0.z;
            Bs[bf][bg4 + 3][bk_] = sb0.w;
            Bs[bf][bg4 + 64][bk_] = sb1.x;
            Bs[bf][bg4 + 65][bk_] = sb1.y;
            Bs[bf][bg4 + 66][bk_] = sb1.z;
            Bs[bf][bg4 + 67][bk_] = sb1.w;
        } else {
            *(float4*)&Bs[bf][ar][ac]      = sb0;
            *(float4*)&Bs[bf][ar + 64][ac] = sb1;
        }
    };

    auto compute = [&](int bf) {
#pragma unroll
        for (int kk = 0; kk < BK; kk += 8) {
            uint32_t ah[4][4], al[4][4], bh[4][2], bl[4][2];
#pragma unroll
            for (int mt = 0; mt < 4; mt++) {
                const float2 t0 = *(const float2*)&As[bf][wm0 + mt * 16 + lr][kk + lc2];
                const float2 t1 = *(const float2*)&As[bf][wm0 + mt * 16 + lr + 8][kk + lc2];
                ah[mt][0] = f2tf32(t0.x); al[mt][0] = __float_as_uint(t0.x - __uint_as_float(ah[mt][0]));
                ah[mt][2] = f2tf32(t0.y); al[mt][2] = __float_as_uint(t0.y - __uint_as_float(ah[mt][2]));
                ah[mt][1] = f2tf32(t1.x); al[mt][1] = __float_as_uint(t1.x - __uint_as_float(ah[mt][1]));
                ah[mt][3] = f2tf32(t1.y); al[mt][3] = __float_as_uint(t1.y - __uint_as_float(ah[mt][3]));
            }
#pragma unroll
            for (int nt = 0; nt < 4; nt++) {
                const float2 t = *(const float2*)&Bs[bf][wn0 + nt * 8 + lr][kk + lc2];
                bh[nt][0] = f2tf32(t.x); bl[nt][0] = __float_as_uint(t.x - __uint_as_float(bh[nt][0]));
                bh[nt][1] = f2tf32(t.y); bl[nt][1] = __float_as_uint(t.y - __uint_as_float(bh[nt][1]));
            }
#pragma unroll
            for (int mt = 0; mt < 4; mt++)
#pragma unroll
                for (int nt = 0; nt < 4; nt++) {
                    mma8(acc[mt][nt], ah[mt], bh[nt]);
                    mma8(acc[mt][nt], al[mt], bh[nt]);
                    mma8(acc[mt][nt], ah[mt], bl[nt]);
                }
        }
    };

    store_tiles(0, a0, a1, b0, b1);
    __syncthreads();

    const int KT = K / BK;
    int buf = 0;
    for (int t = 1; t <= KT; t++) {
        if (t < KT) {
            const int ko = t * BK;
            a0 = *(const float4*)(Ap0 + ko);
            a1 = *(const float4*)(Ap1 + ko);
            if (TRB) {
                b0 = *(const float4*)(Bp0 + (size_t)ko * ldb);
                b1 = *(const float4*)(Bp1 + (size_t)ko * ldb);
            } else {
                b0 = *(const float4*)(Bp0 + ko);
                b1 = *(const float4*)(Bp1 + ko);
            }
        }
        compute(buf);
        if (t < KT) {
            buf ^= 1;
            store_tiles(buf, a0, a1, b0, b1);
            __syncthreads();
        }
    }

    if (EXPSUM) {
        // exp + tf32-round + store + deterministic per-row partial sums
        __syncthreads();                 // smem reads done; reuse As as scratch
        float* red = &As[0][0][0];
#pragma unroll
        for (int mt = 0; mt < 4; mt++) {
#pragma unroll
            for (int h = 0; h < 2; h++) {
                const int rl = wm0 + mt * 16 + lr + 8 * h;
                float* Crow = C + (row0 + rl) * (size_t)ldc + col0;
                float es = 0.f;
#pragma unroll
                for (int nt = 0; nt < 4; nt++) {
                    const int cc = wn0 + nt * 8 + lc2;
                    float2 v;
                    v.x = tf32_round(__expf(acc[mt][nt][h * 2 + 0]));
                    v.y = tf32_round(__expf(acc[mt][nt][h * 2 + 1]));
                    es += v.x + v.y;
                    *(float2*)(Crow + cc) = v;
                }
                es += __shfl_xor_sync(0xffffffffu, es, 1);
                es += __shfl_xor_sync(0xffffffffu, es, 2);
                if ((lane & 3) == 0) red[(wid >> 1) * 128 + rl] = es;
            }
        }
        __syncthreads();
        if (tid < 128) {
            const float s = red[tid] + red[128 + tid] + red[256 + tid] + red[384 + tid];
            part[((size_t)z * 64 + blockIdx.x) * NTOK + row0 + tid] = s;
        }
    } else {
#pragma unroll
        for (int mt = 0; mt < 4; mt++) {
#pragma unroll
            for (int h = 0; h < 2; h++) {
                const size_t r = row0 + wm0 + mt * 16 + lr + h * 8;
                float* Crow = C + r * (size_t)ldc + col0;
#pragma unroll
                for (int nt = 0; nt < 4; nt++) {
                    const int cc = wn0 + nt * 8 + lc2;
                    float2 v;
                    v.x = acc[mt][nt][h * 2 + 0];
                    v.y = acc[mt][nt][h * 2 + 1];
                    *(float2*)(Crow + cc) = v;
                }
            }
        }
    }
}

__global__ void reduce_rinv(const float* __restrict__ part, float* __restrict__ rinv) {
    const int i = blockIdx.x * 256 + threadIdx.x;   // 0..16383
    const int z = i >> 13, r = i & (NTOK - 1);
    const float* p = part + (size_t)z * 64 * NTOK + r;
    float s = 0.f;
#pragma unroll
    for (int b = 0; b < 64; b++) s += p[(size_t)b * NTOK];
    rinv[i] = 1.f / s;
}

// ================= V projection: single-pass tf32 (R4-proven) ================
// 128 threads, block 128x128, warp tile 64x64, transposed-B smem.
__global__ __launch_bounds__(128, 2)
void vproj_gemm(const float* __restrict__ A0, const float* __restrict__ A1, int lda,
                const float* __restrict__ B, int ldb,
                float* __restrict__ C0, float* __restrict__ C1, int ldc, int K)
{
    constexpr int STR = 24;
    __shared__ float As[2][128][STR];
    __shared__ float Bs[2][128][STR];

    const int z = blockIdx.z;
    const float* A = z ? A1 : A0;
    float*       C = z ? C1 : C0;

    const int tid  = threadIdx.x;
    const int lane = tid & 31;
    const int wid  = tid >> 5;
    const int wm0  = (wid & 1) << 6;
    const int wn0  = (wid >> 1) << 6;
    const int lr   = lane >> 2;
    const int lc2  = (lane & 3) << 1;

    const size_t row0 = (size_t)blockIdx.y * 128;
    const size_t col0 = (size_t)blockIdx.x * 128;

    const int arr = tid >> 2;
    const int ac4 = (tid & 3) << 2;
    const float* Apb = A + (row0 + arr) * (size_t)lda + ac4;
    const size_t astr = (size_t)32 * lda;

    const int bk  = tid & 15;
    const int bn0 = (tid >> 4) << 4;
    const float* Bpb = B + (size_t)bk * ldb + col0 + bn0;

    float acc[4][8][4];
#pragma unroll
    for (int i = 0; i < 4; i++)
#pragma unroll
        for (int j = 0; j < 8; j++)
#pragma unroll
            for (int k = 0; k < 4; k++) acc[i][j][k] = 0.f;

    auto stage = [&](int bf, const float4* av, const float4* bv) {
#pragma unroll
        for (int j = 0; j < 4; j++) {
            float4 v = av[j];
            v.x = tf32_round(v.x); v.y = tf32_round(v.y);
            v.z = tf32_round(v.z); v.w = tf32_round(v.w);
            *(float4*)&As[bf][arr + 32 * j][ac4] = v;
        }
#pragma unroll
        for (int i = 0; i < 4; i++) {
            float4 v = bv[i];
            v.x = tf32_round(v.x); v.y = tf32_round(v.y);
            v.z = tf32_round(v.z); v.w = tf32_round(v.w);
            const int nb = bn0 + 4 * i;
            Bs[bf][nb + 0][bk] = v.x;
            Bs[bf][nb + 1][bk] = v.y;
            Bs[bf][nb + 2][bk] = v.z;
            Bs[bf][nb + 3][bk] = v.w;
        }
    };

    float4 av[4], bv[4];
#pragma unroll
    for (int j = 0; j < 4; j++) av[j] = *(const float4*)(Apb + j * astr);
#pragma unroll
    for (int i = 0; i < 4; i++) bv[i] = *(const float4*)(Bpb + 4 * i);
    stage(0, av, bv);
    __syncthreads();

    const int KT = K / 16;
    int buf = 0;
    for (int t = 1; t <= KT; t++) {
        if (t < KT) {
            const size_t ko = (size_t)t * 16;
#pragma unroll
            for (int j = 0; j < 4; j++) av[j] = *(const float4*)(Apb + j * astr + ko);
#pragma unroll
            for (int i = 0; i < 4; i++) bv[i] = *(const float4*)(Bpb + ko * ldb + 4 * i);
        }
#pragma unroll
        for (int kk = 0; kk < 16; kk += 8) {
            uint32_t ah[4][4], bh[8][2];
#pragma unroll
            for (int mt = 0; mt < 4; mt++) {
                const float2 t0 = *(const float2*)&As[buf][wm0 + mt * 16 + lr][kk + lc2];
                const float2 t1 = *(const float2*)&As[buf][wm0 + mt * 16 + lr + 8][kk + lc2];
                ah[mt][0] = __float_as_uint(t0.x);
                ah[mt][1] = __float_as_uint(t1.x);
                ah[mt][2] = __float_as_uint(t0.y);
                ah[mt][3] = __float_as_uint(t1.y);
            }
#pragma unroll
            for (int nt = 0; nt < 8; nt++) {
                const float2 t = *(const float2*)&Bs[buf][wn0 + nt * 8 + lr][kk + lc2];
                bh[nt][0] = __float_as_uint(t.x);
                bh[nt][1] = __float_as_uint(t.y);
            }
#pragma unroll
            for (int mt = 0; mt < 4; mt++)
#pragma unroll
                for (int nt = 0; nt < 8; nt++)
                    mma8(acc[mt][nt], ah[mt], bh[nt]);
        }
        if (t < KT) {
            buf ^= 1;
            stage(buf, av, bv);
            __syncthreads();
        }
    }

#pragma unroll
    for (int mt = 0; mt < 4; mt++) {
#pragma unroll
        for (int h = 0; h < 2; h++) {
            const size_t r = row0 + wm0 + mt * 16 + lr + h * 8;
            float* Crow = C + r * (size_t)ldc + col0;
#pragma unroll
            for (int nt = 0; nt < 8; nt++) {
                const int cc = wn0 + nt * 8 + lc2;
                float2 v;
                v.x = tf32_round(acc[mt][nt][h * 2 + 0]);
                v.y = tf32_round(acc[mt][nt][h * 2 + 1]);
                *(float2*)(Crow + cc) = v;
            }
        }
    }
}

// ================= PV GEMM: 128x256 tile, 256 threads ========================
// Halves the 4x S re-read of the 128x128 version (S reuse is along N).
// Pure-copy staging (S, V already tf32-exact). Epilogue: C = acc*rinv + Res.
// Dynamic smem: As 2*128*24 + Bs 2*256*24 floats = 73728 bytes.
__global__ __launch_bounds__(256, 1)
void pv_gemm(const float* __restrict__ A0, const float* __restrict__ A1,
             const float* __restrict__ B0, const float* __restrict__ B1,
             const float* __restrict__ R0, const float* __restrict__ R1,
             float* __restrict__ C0, float* __restrict__ C1,
             const float* __restrict__ RI)
{
    constexpr int STR = 24;
    extern __shared__ float dsm[];
    float (*As)[128][STR] = (float (*)[128][STR])dsm;            // [2][128][24]
    float (*Bs)[256][STR] = (float (*)[256][STR])(dsm + 2 * 128 * STR);

    const int z = blockIdx.z;
    const float* A   = z ? A1 : A0;     // S [NTOK x NTOK]
    const float* B   = z ? B1 : B0;     // V [NTOK x CDIM]
    const float* Res = z ? R1 : R0;
    float*       C   = z ? C1 : C0;

    const int tid  = threadIdx.x;
    const int lane = tid & 31;
    const int wid  = tid >> 5;          // 0..7
    const int wm0  = (wid & 1) << 6;    // 0,64
    const int wn0  = (wid >> 1) << 6;   // 0,64,128,192
    const int lr   = lane >> 2;
    const int lc2  = (lane & 3) << 1;

    const size_t row0 = (size_t)blockIdx.y * 128;
    const size_t col0 = (size_t)blockIdx.x * 256;

    // A loader: 128x16 floats, 8 per thread (2 float4)
    const int arr = tid >> 1;                   // 0..127
    const int ac8 = (tid & 1) << 3;             // 0,8
    const float* Apb = A + (row0 + arr) * (size_t)NTOK + ac8;

    // B loader: 16x256 floats, 16 per thread (4 float4), transposed store
    const int bk  = tid & 15;
    const int bn0 = (tid >> 4) << 4;            // 0..240
    const float* Bpb = B + (size_t)bk * CDIM + col0 + bn0;

    float acc[4][8][4];
#pragma unroll
    for (int i = 0; i < 4; i++)
#pragma unroll
        for (int j = 0; j < 8; j++)
#pragma unroll
            for (int k = 0; k < 4; k++) acc[i][j][k] = 0.f;

    auto stage = [&](int bf, const float4* av, const float4* bv) {
        *(float4*)&As[bf][arr][ac8]     = av[0];
        *(float4*)&As[bf][arr][ac8 + 4] = av[1];
#pragma unroll
        for (int i = 0; i < 4; i++) {
            const float4 v = bv[i];
            const int nb = bn0 + 4 * i;
            Bs[bf][nb + 0][bk] = v.x;
            Bs[bf][nb + 1][bk] = v.y;
            Bs[bf][nb + 2][bk] = v.z;
            Bs[bf][nb + 3][bk] = v.w;
        }
    };

    float4 av[2], bv[4];
    av[0] = *(const float4*)Apb;
    av[1] = *(const float4*)(Apb + 4);
#pragma unroll
    for (int i = 0; i < 4; i++) bv[i] = *(const float4*)(Bpb + 4 * i);
    stage(0, av, bv);
    __syncthreads();

    const int KT = NTOK / 16;
    int buf = 0;
    for (int t = 1; t <= KT; t++) {
        if (t < KT) {
            const size_t ko = (size_t)t * 16;
            av[0] = *(const float4*)(Apb + ko);
            av[1] = *(const float4*)(Apb + ko + 4);
            const float* bp = Bpb + ko * CDIM;
#pragma unroll
            for (int i = 0; i < 4; i++) bv[i] = *(const float4*)(bp + 4 * i);
        }
#pragma unroll
        for (int kk = 0; kk < 16; kk += 8) {
            uint32_t ah[4][4], bh[8][2];
#pragma unroll
            for (int mt = 0; mt < 4; mt++) {
                const float2 t0 = *(const float2*)&As[buf][wm0 + mt * 16 + lr][kk + lc2];
                const float2 t1 = *(const float2*)&As[buf][wm0 + mt * 16 + lr + 8][kk + lc2];
                ah[mt][0] = __float_as_uint(t0.x);
                ah[mt][1] = __float_as_uint(t1.x);
                ah[mt][2] = __float_as_uint(t0.y);
                ah[mt][3] = __float_as_uint(t1.y);
            }
#pragma unroll
            for (int nt = 0; nt < 8; nt++) {
                const float2 t = *(const float2*)&Bs[buf][wn0 + nt * 8 + lr][kk + lc2];
                bh[nt][0] = __float_as_uint(t.x);
                bh[nt][1] = __float_as_uint(t.y);
            }
#pragma unroll
            for (int mt = 0; mt < 4; mt++)
#pragma unroll
                for (int nt = 0; nt < 8; nt++)
                    mma8(acc[mt][nt], ah[mt], bh[nt]);
        }
        if (t < KT) {
            buf ^= 1;
            stage(buf, av, bv);
            __syncthreads();
        }
    }

    // epilogue: scale by rinv, add residual
#pragma unroll
    for (int mt = 0; mt < 4; mt++) {
#pragma unroll
        for (int h = 0; h < 2; h++) {
            const size_t r = row0 + wm0 + mt * 16 + lr + h * 8;
            const float scale = RI[(size_t)z * NTOK + r];
            float* Crow = C + r * (size_t)CDIM + col0;
            const float* Rrow = Res + r * (size_t)CDIM + col0;
#pragma unroll
            for (int nt = 0; nt < 8; nt++) {
                const int cc = wn0 + nt * 8 + lc2;
                const float2 rv = *(const float2*)(Rrow + cc);
                float2 v;
                v.x = acc[mt][nt][h * 2 + 0] * scale + rv.x;
                v.y = acc[mt][nt][h * 2 + 1] * scale + rv.y;
                *(float2*)(Crow + cc) = v;
            }
        }
    }
}

// ---------------- launch -----------------------------------------------------
extern "C" void kernel_launch(void* const* d_in, const int* in_sizes, int n_in,
                              void* d_out, int out_size)
{
    const float* im1 = (const float*)d_in[0];
    const float* im2 = (const float*)d_in[1];
    const float* Wq  = (const float*)d_in[2];
    const float* Wk  = (const float*)d_in[3];
    const float* Wv  = (const float*)d_in[4];

    float* out1 = (float*)d_out;
    float* out2 = out1 + (size_t)NTOK * CDIM;

    float *pS1, *pS2, *pQK1, *pQK2, *pV1, *pV2, *pWqk, *pPart, *pRinv;
    cudaGetSymbolAddress((void**)&pS1,   g_S1);
    cudaGetSymbolAddress((void**)&pS2,   g_S2);
    cudaGetSymbolAddress((void**)&pQK1,  g_QK1);
    cudaGetSymbolAddress((void**)&pQK2,  g_QK2);
    cudaGetSymbolAddress((void**)&pV1,   g_V1);
    cudaGetSymbolAddress((void**)&pV2,   g_V2);
    cudaGetSymbolAddress((void**)&pWqk,  g_Wqk);
    cudaGetSymbolAddress((void**)&pPart, g_part);
    cudaGetSymbolAddress((void**)&pRinv, g_rinv);

    const int PV_SMEM = (2 * 128 * 24 + 2 * 256 * 24) * 4;   // 73728 B
    cudaFuncSetAttribute(pv_gemm, cudaFuncAttributeMaxDynamicSharedMemorySize, PV_SMEM);

    pack_wqk<<<256, 256>>>(Wq, Wk, pWqk);

    // Q/K projections (3xTF32, near-fp32): [Q|K]z = imz @ [Wq|Wk]
    gemm3x<true, false><<<dim3(1, 64, 2), 256>>>(im1, im2, CDIM, pWqk, pWqk, 128,
                                                 pQK1, pQK2, 128, CDIM, nullptr);
    // V projections (single-pass tf32, rna staging, rounded outputs)
    vproj_gemm<<<dim3(4, 64, 2), 128>>>(im1, im2, CDIM, Wv, CDIM,
                                        pV1, pV2, CDIM, CDIM);
    // logits + fused exp + partial row sums: S1 = exp(Q2 K1^T), S2 = exp(Q1 K2^T)
    gemm3x<false, true><<<dim3(64, 64, 2), 256>>>(pQK2, pQK1, 128, pQK1 + 64, pQK2 + 64, 128,
                                                  pS1, pS2, NTOK, 64, pPart);
    reduce_rinv<<<64, 256>>>(pPart, pRinv);
    // PV: out = (S @ V) * rinv + im    (128x256 tiles halve S re-reads)
    pv_gemm<<<dim3(2, 64, 2), 256, PV_SMEM>>>(pS1, pS2, pV1, pV2,
                                              im1, im2, out1, out2, pRinv);
}